// round 1
// baseline (speedup 1.0000x reference)
#include <cuda_runtime.h>
#include <cstdint>

#define P_NUM 65536
#define B_NUM 8
#define G_NUM 64
#define NROWS 8
#define TPB   128
#define PRIORS_PER_BLOCK (TPB * NROWS)   // 1024

// Packed per-(b,g) argmax over priors: (iou_bits << 32) | (0xFFFFFFFF - p)
// max => highest iou, then lowest p (first-occurrence tie-break like jnp.argmax).
__device__ unsigned long long g_best[B_NUM * G_NUM];

__global__ void reset_kernel() {
    int i = threadIdx.x;
    if (i < B_NUM * G_NUM) g_best[i] = 0xFFFFFFFFull;  // iou=0, p=0 default
}

__global__ __launch_bounds__(TPB)
void match_main_kernel(const float4* __restrict__ priors,    // [P]
                       const float4* __restrict__ gt_boxes,  // [B*G]
                       const int*    __restrict__ gt_labels, // [B*G]
                       float* __restrict__ out_loc,          // [B*P*4]
                       float* __restrict__ out_conf)         // [B*P] or null
{
    __shared__ float4 s_box[G_NUM];
    __shared__ float  s_area[G_NUM];
    __shared__ int    s_lab[G_NUM];
    __shared__ unsigned long long s_best[G_NUM];

    const int b   = blockIdx.y;
    const int tid = threadIdx.x;

    if (tid < G_NUM) {
        float4 g4 = gt_boxes[b * G_NUM + tid];
        s_box[tid]  = g4;
        s_area[tid] = (g4.z - g4.x) * (g4.w - g4.y);
        s_lab[tid]  = gt_labels[b * G_NUM + tid];
        s_best[tid] = 0ull;
    }
    __syncthreads();

    const int lane = tid & 31;
    const int warp = tid >> 5;
    const int warp_base = blockIdx.x * PRIORS_PER_BLOCK + warp * (32 * NROWS);

    float4 pr[NROWS];
    float  pa[NROWS];
    float  best_iou[NROWS];
    int    best_g[NROWS];
#pragma unroll
    for (int r = 0; r < NROWS; r++) {
        pr[r] = priors[warp_base + 32 * r + lane];
        pa[r] = (pr[r].z - pr[r].x) * (pr[r].w - pr[r].y);
        best_iou[r] = -1.0f;
        best_g[r]   = 0;
    }

    for (int g = 0; g < G_NUM; g++) {
        const float4 gb = s_box[g];
        const float  ga = s_area[g];
        float lmax = -1.0f;
        int   lr   = 0;
#pragma unroll
        for (int r = 0; r < NROWS; r++) {
            // Exact op order of the reference IoU (bit-exact selection keys).
            float ltx = fmaxf(pr[r].x, gb.x);
            float lty = fmaxf(pr[r].y, gb.y);
            float rbx = fminf(pr[r].z, gb.z);
            float rby = fminf(pr[r].w, gb.w);
            float wx  = fmaxf(rbx - ltx, 0.0f);
            float wy  = fmaxf(rby - lty, 0.0f);
            float inter = wx * wy;
            float uni   = (pa[r] + ga) - inter;   // area_a + area_b - inter
            float iou   = inter / uni;            // IEEE div.rn (no fast math)
            if (iou > best_iou[r]) { best_iou[r] = iou; best_g[r] = g; }  // first max wins
            if (iou > lmax)        { lmax = iou;        lr = r;        }  // lowest p wins
        }
        // Column (per-GT) argmax over this warp's 256 priors.
        unsigned int lbits = __float_as_uint(lmax);              // lmax >= 0 -> monotone bits
        unsigned int wbits = __reduce_max_sync(0xffffffffu, lbits);
        unsigned int candp = (lbits == wbits)
                               ? (unsigned int)(warp_base + 32 * lr + lane)
                               : 0xFFFFFFFFu;
        unsigned int wp = __reduce_min_sync(0xffffffffu, candp); // smallest p among maxima
        if (lane == 0) {
            unsigned long long key =
                ((unsigned long long)wbits << 32) | (unsigned long long)(0xFFFFFFFFu - wp);
            atomicMax(&s_best[g], key);
        }
    }

    // Emit per-prior results (forced priors fixed up by kernel 3).
#pragma unroll
    for (int r = 0; r < NROWS; r++) {
        const int p = warp_base + 32 * r + lane;
        const float4 m = s_box[best_g[r]];
        const int cv = (best_iou[r] < 0.5f) ? 0 : (s_lab[best_g[r]] + 1);

        float pcx = (pr[r].x + pr[r].z) * 0.5f;
        float pcy = (pr[r].y + pr[r].w) * 0.5f;
        float pw  = pr[r].z - pr[r].x;
        float ph  = pr[r].w - pr[r].y;
        float gcx = (m.x + m.z) * 0.5f;
        float gcy = (m.y + m.w) * 0.5f;
        float gw  = m.z - m.x;
        float gh  = m.w - m.y;

        float4 loc;
        loc.x = (gcx - pcx) / (0.1f * pw);
        loc.y = (gcy - pcy) / (0.1f * ph);
        loc.z = logf(gw / pw) / 0.2f;
        loc.w = logf(gh / ph) / 0.2f;

        reinterpret_cast<float4*>(out_loc)[(size_t)b * P_NUM + p] = loc;
        if (out_conf) out_conf[(size_t)b * P_NUM + p] = (float)cv;
    }

    __syncthreads();
    if (tid < G_NUM) atomicMax(&g_best[b * G_NUM + tid], s_best[tid]);
}

// Replicates: best_gt_iou.at[best_prior_idx].set(2.0);
//             best_gt_idx.at[best_prior_idx].set(arange(G))
// Sequential-scatter semantics: for duplicate priors, the LAST g wins.
__global__ void fixup_kernel(const float4* __restrict__ priors,
                             const float4* __restrict__ gt_boxes,
                             const int*    __restrict__ gt_labels,
                             float* __restrict__ out_loc,
                             float* __restrict__ out_conf)
{
    __shared__ unsigned int sp[B_NUM * G_NUM];
    const int tid = threadIdx.x;             // 512 threads = (b,g)
    const unsigned long long key = g_best[tid];
    const unsigned int p = 0xFFFFFFFFu - (unsigned int)(key & 0xFFFFFFFFull);
    sp[tid] = p;
    __syncthreads();

    const int b = tid >> 6;
    const int g = tid & 63;
    bool win = true;
    for (int g2 = g + 1; g2 < G_NUM; g2++)
        if (sp[(b << 6) + g2] == p) win = false;
    if (!win) return;

    const float4 m  = gt_boxes[b * G_NUM + g];
    const float4 pb = priors[p];

    float pcx = (pb.x + pb.z) * 0.5f;
    float pcy = (pb.y + pb.w) * 0.5f;
    float pw  = pb.z - pb.x;
    float ph  = pb.w - pb.y;
    float gcx = (m.x + m.z) * 0.5f;
    float gcy = (m.y + m.w) * 0.5f;
    float gw  = m.z - m.x;
    float gh  = m.w - m.y;

    float4 loc;
    loc.x = (gcx - pcx) / (0.1f * pw);
    loc.y = (gcy - pcy) / (0.1f * ph);
    loc.z = logf(gw / pw) / 0.2f;
    loc.w = logf(gh / ph) / 0.2f;

    reinterpret_cast<float4*>(out_loc)[(size_t)b * P_NUM + p] = loc;
    if (out_conf) out_conf[(size_t)b * P_NUM + p] = (float)(gt_labels[b * G_NUM + g] + 1);
}

extern "C" void kernel_launch(void* const* d_in, const int* in_sizes, int n_in,
                              void* d_out, int out_size)
{
    const float4* priors    = (const float4*)d_in[0];   // [P,4] f32
    const float4* gt_boxes  = (const float4*)d_in[1];   // [B,G,4] f32
    const int*    gt_labels = (const int*)d_in[2];      // [B,G] i32

    float* out = (float*)d_out;
    float* out_loc  = out;                                           // [B,P,4]
    float* out_conf = (out_size >= B_NUM * P_NUM * 5)
                        ? out + (size_t)B_NUM * P_NUM * 4 : nullptr; // [B,P]

    reset_kernel<<<1, 512>>>();
    dim3 grid(P_NUM / PRIORS_PER_BLOCK, B_NUM);   // (64, 8)
    match_main_kernel<<<grid, TPB>>>(priors, gt_boxes, gt_labels, out_loc, out_conf);
    fixup_kernel<<<1, B_NUM * G_NUM>>>(priors, gt_boxes, gt_labels, out_loc, out_conf);
}

// round 2
// speedup vs baseline: 1.6862x; 1.6862x over previous
#include <cuda_runtime.h>
#include <cstdint>

#define P_NUM 65536
#define B_NUM 8
#define G_NUM 64
#define NBX 16
#define NBY 16
#define NBINS (NBX * NBY)                 // 256
#define SLOT_CAP (P_NUM + NBINS * 31)     // 73472 (padded-to-32 worst case)
#define INVALID_P 0xFFFFFFFFu

// ---------------- persistent device scratch ----------------
__device__ unsigned int       d_bin_count[NBINS];
__device__ unsigned int       d_bin_off[NBINS];
__device__ int                d_bbox_min[NBINS][2];   // x0,y0 bits (positive floats)
__device__ int                d_bbox_max[NBINS][2];   // x1,y1 bits
__device__ unsigned short     d_slot_bin[SLOT_CAP];
__device__ unsigned int       d_perm_idx[SLOT_CAP];
__device__ float4             d_perm_pri[SLOT_CAP];
__device__ unsigned int       d_prior_bin[P_NUM];
__device__ unsigned int       d_prior_rank[P_NUM];
__device__ unsigned char      d_cand[B_NUM * NBINS * G_NUM];
__device__ unsigned int       d_cand_cnt[B_NUM * NBINS];
__device__ unsigned long long g_best[B_NUM * G_NUM];  // .bss zero == reset state

// ---------------- phase A0: init + prefill padding ----------------
__global__ void k_init(void)
{
    int gid = blockIdx.x * 256 + threadIdx.x;   // covers SLOT_CAP exactly
    d_slot_bin[gid] = 0xFFFF;
    d_perm_idx[gid] = INVALID_P;
    d_perm_pri[gid] = make_float4(-10.0f, -10.0f, -9.9f, -9.9f);  // IoU==0 with any GT
    if (blockIdx.x == 0 && threadIdx.x < NBINS) {
        d_bin_count[threadIdx.x]  = 0;
        d_bbox_min[threadIdx.x][0] = 0x7F800000;  // +inf
        d_bbox_min[threadIdx.x][1] = 0x7F800000;
        d_bbox_max[threadIdx.x][0] = 0;
        d_bbox_max[threadIdx.x][1] = 0;
    }
}

// ---------------- phase A: bin priors, count, bbox ----------------
__global__ void k_bin(const float4* __restrict__ priors)
{
    int p = blockIdx.x * 256 + threadIdx.x;
    float4 pr = priors[p];
    float cx = (pr.x + pr.z) * 0.5f;
    float cy = (pr.y + pr.w) * 0.5f;
    int bx = (int)((cx - 0.1f) * (NBX / 0.8f));
    int by = (int)((cy - 0.1f) * (NBY / 0.8f));
    bx = bx < 0 ? 0 : (bx > NBX - 1 ? NBX - 1 : bx);
    by = by < 0 ? 0 : (by > NBY - 1 ? NBY - 1 : by);
    int bin = by * NBX + bx;
    unsigned int rank = atomicAdd(&d_bin_count[bin], 1u);
    d_prior_bin[p]  = bin;
    d_prior_rank[p] = rank;
    // positive floats: int compare == float compare
    atomicMin(&d_bbox_min[bin][0], __float_as_int(pr.x));
    atomicMin(&d_bbox_min[bin][1], __float_as_int(pr.y));
    atomicMax(&d_bbox_max[bin][0], __float_as_int(pr.z));
    atomicMax(&d_bbox_max[bin][1], __float_as_int(pr.w));
}

// ---------------- phase BD: block0 = scan, blocks 1..8 = candidate lists ----------------
__global__ void k_scan_cand(const float4* __restrict__ gt_boxes)
{
    if (blockIdx.x == 0) {
        __shared__ unsigned int s[NBINS];
        int t = threadIdx.x;
        unsigned int padded = (d_bin_count[t] + 31u) & ~31u;
        s[t] = padded;
        __syncthreads();
        for (int d = 1; d < NBINS; d <<= 1) {
            unsigned int v = (t >= d) ? s[t - d] : 0u;
            __syncthreads();
            s[t] += v;
            __syncthreads();
        }
        d_bin_off[t] = s[t] - padded;   // exclusive scan
    } else {
        int pair = (blockIdx.x - 1) * 256 + threadIdx.x;   // 0..2047
        int b   = pair >> 8;
        int bin = pair & (NBINS - 1);
        float minx0 = __int_as_float(d_bbox_min[bin][0]);
        float miny0 = __int_as_float(d_bbox_min[bin][1]);
        float maxx1 = __int_as_float(d_bbox_max[bin][0]);
        float maxy1 = __int_as_float(d_bbox_max[bin][1]);
        unsigned int cnt = 0;
        unsigned char* lst = &d_cand[pair * G_NUM];
        for (int g = 0; g < G_NUM; g++) {
            float4 gb = gt_boxes[b * G_NUM + g];
            // conservative & exact: skipped pairs have intersection exactly 0
            bool reject = (gb.z <= minx0) | (gb.x >= maxx1) |
                          (gb.w <= miny0) | (gb.y >= maxy1);
            if (!reject) lst[cnt++] = (unsigned char)g;
        }
        d_cand_cnt[pair] = cnt;
    }
}

// ---------------- phase C: scatter permutation ----------------
__global__ void k_scatter(const float4* __restrict__ priors)
{
    int p = blockIdx.x * 256 + threadIdx.x;
    unsigned int bin  = d_prior_bin[p];
    unsigned int slot = d_bin_off[bin] + d_prior_rank[p];
    d_slot_bin[slot] = (unsigned short)bin;
    d_perm_idx[slot] = (unsigned int)p;
    d_perm_pri[slot] = priors[p];
}

// ---------------- phase E: main matching ----------------
__global__ __launch_bounds__(256)
void k_match(const float4* __restrict__ gt_boxes,
             const int*    __restrict__ gt_labels,
             float* __restrict__ out_loc,
             float* __restrict__ out_conf)
{
    __shared__ float4 s_box[G_NUM];
    __shared__ float  s_area[G_NUM];
    __shared__ int    s_lab[G_NUM];
    __shared__ unsigned long long s_best[G_NUM];

    const int b   = blockIdx.y;
    const int tid = threadIdx.x;
    const int lane = tid & 31;

    if (tid < G_NUM) {
        float4 g4 = gt_boxes[b * G_NUM + tid];
        s_box[tid]  = g4;
        s_area[tid] = (g4.z - g4.x) * (g4.w - g4.y);
        s_lab[tid]  = gt_labels[b * G_NUM + tid];
        s_best[tid] = 0ull;
    }
    __syncthreads();

    const int slot = blockIdx.x * 256 + tid;
    int binv = (int)d_slot_bin[slot];
    int bin  = __shfl_sync(0xffffffffu, binv, 0);   // warp-uniform (pad32 guarantees)

    if (bin != 0xFFFF) {
        const unsigned int p  = d_perm_idx[slot];
        const float4 pr = d_perm_pri[slot];
        const float  pa = (pr.z - pr.x) * (pr.w - pr.y);

        float best_iou = 0.0f;   // all-zero column -> g=0, matching jnp.argmax
        int   best_g   = 0;

        const int pair = (b << 8) | bin;
        const unsigned int cnt = d_cand_cnt[pair];
        const unsigned char* lst = &d_cand[pair * G_NUM];

        for (unsigned int j = 0; j < cnt; j++) {
            const int g = lst[j];                     // ascending g order
            const float4 gb = s_box[g];
            const float  ga = s_area[g];
            float ltx = fmaxf(pr.x, gb.x);
            float lty = fmaxf(pr.y, gb.y);
            float rbx = fminf(pr.z, gb.z);
            float rby = fminf(pr.w, gb.w);
            float wx  = fmaxf(rbx - ltx, 0.0f);
            float wy  = fmaxf(rby - lty, 0.0f);
            float inter = wx * wy;
            float uni   = (pa + ga) - inter;
            float iou   = inter / uni;
            if (iou > best_iou) { best_iou = iou; best_g = g; }  // first max wins

            // per-GT column argmax across this warp (iou >= 0 -> bits monotone)
            unsigned int ub = __float_as_uint(iou);
            unsigned int wb = __reduce_max_sync(0xffffffffu, ub);
            unsigned int candp = (ub == wb) ? p : INVALID_P;     // pad lanes: p==INVALID
            unsigned int mp = __reduce_min_sync(0xffffffffu, candp);
            if (lane == 0 && wb != 0u) {
                unsigned long long key =
                    ((unsigned long long)wb << 32) | (unsigned long long)(~mp);
                atomicMax(&s_best[g], key);
            }
        }

        if (p != INVALID_P) {
            const float4 m  = s_box[best_g];
            const int    cv = (best_iou < 0.5f) ? 0 : (s_lab[best_g] + 1);
            float pcx = (pr.x + pr.z) * 0.5f;
            float pcy = (pr.y + pr.w) * 0.5f;
            float pw  = pr.z - pr.x;
            float ph  = pr.w - pr.y;
            float gcx = (m.x + m.z) * 0.5f;
            float gcy = (m.y + m.w) * 0.5f;
            float gw  = m.z - m.x;
            float gh  = m.w - m.y;
            float4 loc;
            loc.x = (gcx - pcx) / (0.1f * pw);
            loc.y = (gcy - pcy) / (0.1f * ph);
            loc.z = logf(gw / pw) / 0.2f;
            loc.w = logf(gh / ph) / 0.2f;
            reinterpret_cast<float4*>(out_loc)[(size_t)b * P_NUM + p] = loc;
            if (out_conf) out_conf[(size_t)b * P_NUM + p] = (float)cv;
        }
    }

    __syncthreads();
    if (tid < G_NUM) {
        unsigned long long v = s_best[tid];
        if (v) atomicMax(&g_best[(b << 6) + tid], v);
    }
}

// ---------------- phase F: forced-prior fixup + reset for next replay ----------------
// Replicates scatter semantics: for duplicate priors, the LAST g wins.
__global__ void k_fixup(const float4* __restrict__ priors,
                        const float4* __restrict__ gt_boxes,
                        const int*    __restrict__ gt_labels,
                        float* __restrict__ out_loc,
                        float* __restrict__ out_conf)
{
    __shared__ unsigned int sp[B_NUM * G_NUM];
    const int tid = threadIdx.x;             // 512 threads = (b,g)
    const unsigned long long key = g_best[tid];
    g_best[tid] = 0ull;                      // reset == first-call .bss state
    const unsigned int p = ~((unsigned int)(key & 0xFFFFFFFFull));
    sp[tid] = p;
    __syncthreads();

    if (key == 0ull) return;                 // GT matched nothing (cannot happen here)

    const int b = tid >> 6;
    const int g = tid & 63;
    for (int g2 = g + 1; g2 < G_NUM; g2++)
        if (sp[(b << 6) + g2] == p) return;  // a later g claims the same prior

    const float4 m  = gt_boxes[b * G_NUM + g];
    const float4 pb = priors[p];
    float pcx = (pb.x + pb.z) * 0.5f;
    float pcy = (pb.y + pb.w) * 0.5f;
    float pw  = pb.z - pb.x;
    float ph  = pb.w - pb.y;
    float gcx = (m.x + m.z) * 0.5f;
    float gcy = (m.y + m.w) * 0.5f;
    float gw  = m.z - m.x;
    float gh  = m.w - m.y;
    float4 loc;
    loc.x = (gcx - pcx) / (0.1f * pw);
    loc.y = (gcy - pcy) / (0.1f * ph);
    loc.z = logf(gw / pw) / 0.2f;
    loc.w = logf(gh / ph) / 0.2f;
    reinterpret_cast<float4*>(out_loc)[(size_t)b * P_NUM + p] = loc;
    if (out_conf) out_conf[(size_t)b * P_NUM + p] = (float)(gt_labels[b * G_NUM + g] + 1);
}

extern "C" void kernel_launch(void* const* d_in, const int* in_sizes, int n_in,
                              void* d_out, int out_size)
{
    const float4* priors    = (const float4*)d_in[0];   // [P,4] f32
    const float4* gt_boxes  = (const float4*)d_in[1];   // [B,G,4] f32
    const int*    gt_labels = (const int*)d_in[2];      // [B,G] i32

    float* out = (float*)d_out;
    float* out_loc  = out;                                           // [B,P,4]
    float* out_conf = (out_size >= B_NUM * P_NUM * 5)
                        ? out + (size_t)B_NUM * P_NUM * 4 : nullptr; // [B,P]

    k_init     <<<SLOT_CAP / 256, 256>>>();
    k_bin      <<<P_NUM / 256, 256>>>(priors);
    k_scan_cand<<<1 + (B_NUM * NBINS) / 256, 256>>>(gt_boxes);
    k_scatter  <<<P_NUM / 256, 256>>>(priors);
    dim3 grid(SLOT_CAP / 256, B_NUM);                                // (287, 8)
    k_match    <<<grid, 256>>>(gt_boxes, gt_labels, out_loc, out_conf);
    k_fixup    <<<1, B_NUM * G_NUM>>>(priors, gt_boxes, gt_labels, out_loc, out_conf);
}

// round 3
// speedup vs baseline: 2.2342x; 1.3250x over previous
#include <cuda_runtime.h>
#include <cstdint>

#define P_NUM 65536
#define B_NUM 8
#define G_NUM 64
#define NBX 16
#define NBY 16
#define NBINS (NBX * NBY)                 // 256
#define SLOT_CAP (P_NUM + NBINS * 31)     // 73472
#define INVALID_P 0xFFFFFFFFu
#define ENC_MIN(bits) (0x7F800000 - (bits))   // zero-init == +inf identity

// ---------------- persistent device scratch (.bss zero == reset state) ----
__device__ unsigned int       d_bin_count[NBINS];     // reset by k_fixup
__device__ int                d_bb_enc[4][NBINS];     // encMinX,encMinY,maxX,maxY; reset by k_fixup
__device__ unsigned int       d_bin_off[NBINS];
__device__ unsigned int       d_total;                // total padded slots (mult of 32)
__device__ unsigned int       d_binrank[P_NUM];       // bin<<24 | rank
__device__ unsigned short     d_slot_bin[SLOT_CAP];
__device__ unsigned int       d_perm_idx[SLOT_CAP];
__device__ unsigned long long d_cand_mask[B_NUM * NBINS];
__device__ unsigned long long g_best[B_NUM * G_NUM];  // reset by k_fixup

// ---------------- phase A: bin priors (smem-aggregated) ----------------
__global__ __launch_bounds__(256)
void k_bin(const float4* __restrict__ priors)
{
    __shared__ unsigned int s_cnt[NBINS];
    __shared__ int          s_bb[4][NBINS];
    __shared__ unsigned int s_base[NBINS];
    const int tid = threadIdx.x;
    s_cnt[tid] = 0;
    s_bb[0][tid] = 0; s_bb[1][tid] = 0; s_bb[2][tid] = 0; s_bb[3][tid] = 0;
    __syncthreads();

    const int p = blockIdx.x * 256 + tid;
    float4 pr = priors[p];
    float cx = (pr.x + pr.z) * 0.5f;
    float cy = (pr.y + pr.w) * 0.5f;
    int bx = (int)((cx - 0.1f) * (NBX / 0.8f));
    int by = (int)((cy - 0.1f) * (NBY / 0.8f));
    bx = bx < 0 ? 0 : (bx > NBX - 1 ? NBX - 1 : bx);
    by = by < 0 ? 0 : (by > NBY - 1 ? NBY - 1 : by);
    const int bin = by * NBX + bx;
    unsigned int lrank = atomicAdd(&s_cnt[bin], 1u);
    atomicMax(&s_bb[0][bin], ENC_MIN(__float_as_int(pr.x)));
    atomicMax(&s_bb[1][bin], ENC_MIN(__float_as_int(pr.y)));
    atomicMax(&s_bb[2][bin], __float_as_int(pr.z));
    atomicMax(&s_bb[3][bin], __float_as_int(pr.w));
    __syncthreads();

    if (s_cnt[tid] > 0) {
        s_base[tid] = atomicAdd(&d_bin_count[tid], s_cnt[tid]);
        atomicMax(&d_bb_enc[0][tid], s_bb[0][tid]);
        atomicMax(&d_bb_enc[1][tid], s_bb[1][tid]);
        atomicMax(&d_bb_enc[2][tid], s_bb[2][tid]);
        atomicMax(&d_bb_enc[3][tid], s_bb[3][tid]);
    }
    __syncthreads();

    d_binrank[p] = ((unsigned int)bin << 24) | (s_base[bin] + lrank);
}

// ---------------- phase B: block0 = scan + pad; blocks 1..8 = GT masks ----
__global__ __launch_bounds__(256)
void k_scan_cand(const float4* __restrict__ gt_boxes)
{
    const int tid = threadIdx.x;
    if (blockIdx.x == 0) {
        __shared__ unsigned int s[NBINS];
        unsigned int cnt = d_bin_count[tid];
        unsigned int padded = (cnt + 31u) & ~31u;
        s[tid] = padded;
        __syncthreads();
        for (int d = 1; d < NBINS; d <<= 1) {
            unsigned int v = (tid >= d) ? s[tid - d] : 0u;
            __syncthreads();
            s[tid] += v;
            __syncthreads();
        }
        unsigned int off = s[tid] - padded;     // exclusive
        d_bin_off[tid] = off;
        if (tid == NBINS - 1) d_total = s[tid];
        for (unsigned int k = cnt; k < padded; k++)   // pad slots
            d_perm_idx[off + k] = INVALID_P;
    } else {
        __shared__ float4 sg[G_NUM];
        const int b = blockIdx.x - 1;
        if (tid < G_NUM) sg[tid] = gt_boxes[b * G_NUM + tid];
        __syncthreads();
        const int bin = tid;
        float minx0 = __int_as_float(ENC_MIN(d_bb_enc[0][bin]));
        float miny0 = __int_as_float(ENC_MIN(d_bb_enc[1][bin]));
        float maxx1 = __int_as_float(d_bb_enc[2][bin]);
        float maxy1 = __int_as_float(d_bb_enc[3][bin]);
        unsigned long long mask = 0ull;
        for (int g = 0; g < G_NUM; g++) {
            float4 gb = sg[g];
            // exact conservative reject: skipped pairs have intersection == 0
            bool keep = (gb.z > minx0) & (gb.x < maxx1) &
                        (gb.w > miny0) & (gb.y < maxy1);
            if (keep) mask |= 1ull << g;
        }
        d_cand_mask[(b << 8) | bin] = mask;
    }
}

// ---------------- phase C: scatter permutation (small scattered writes) --
__global__ __launch_bounds__(256)
void k_scatter(void)
{
    const int p = blockIdx.x * 256 + threadIdx.x;
    unsigned int br = d_binrank[p];
    unsigned int bin = br >> 24;
    unsigned int slot = d_bin_off[bin] + (br & 0xFFFFFFu);
    d_perm_idx[slot] = (unsigned int)p;
    d_slot_bin[slot] = (unsigned short)bin;
}

// ---------------- phase D: main matching ----------------
__global__ __launch_bounds__(256)
void k_match(const float4* __restrict__ priors,
             const float4* __restrict__ gt_boxes,
             const int*    __restrict__ gt_labels,
             float* __restrict__ out_loc,
             float* __restrict__ out_conf)
{
    __shared__ float4 s_box[G_NUM];
    __shared__ float  s_area[G_NUM];
    __shared__ int    s_lab[G_NUM];
    __shared__ unsigned long long s_best[G_NUM];

    const int b    = blockIdx.y;
    const int tid  = threadIdx.x;
    const int lane = tid & 31;

    if (tid < G_NUM) {
        float4 g4 = gt_boxes[b * G_NUM + tid];
        s_box[tid]  = g4;
        s_area[tid] = (g4.z - g4.x) * (g4.w - g4.y);
        s_lab[tid]  = gt_labels[b * G_NUM + tid];
        s_best[tid] = 0ull;
    }
    __syncthreads();

    const unsigned int slot = blockIdx.x * 256 + tid;
    if (slot < d_total) {                               // warp-uniform (total % 32 == 0)
        const unsigned int p = d_perm_idx[slot];
        const int bin = __shfl_sync(0xffffffffu, (int)d_slot_bin[slot], 0);

        float4 pr;
        if (p != INVALID_P) pr = priors[p];
        else                pr = make_float4(-10.0f, -10.0f, -9.9f, -9.9f); // IoU == 0
        const float pa = (pr.z - pr.x) * (pr.w - pr.y);

        float best_iou = 0.0f;        // all-zero column -> g=0 (jnp.argmax)
        int   best_g   = 0;

        unsigned long long m = d_cand_mask[(b << 8) | bin];
        while (m) {
            const int g = __ffsll((long long)m) - 1;    // ascending g
            m &= m - 1;
            const float4 gb = s_box[g];
            const float  ga = s_area[g];
            float ltx = fmaxf(pr.x, gb.x);
            float lty = fmaxf(pr.y, gb.y);
            float rbx = fminf(pr.z, gb.z);
            float rby = fminf(pr.w, gb.w);
            float wx  = fmaxf(rbx - ltx, 0.0f);
            float wy  = fmaxf(rby - lty, 0.0f);
            float inter = wx * wy;
            float uni   = (pa + ga) - inter;
            float iou   = inter / uni;
            if (iou > best_iou) { best_iou = iou; best_g = g; }  // first max wins

            unsigned int ub = __float_as_uint(iou);              // iou >= 0: monotone bits
            unsigned int wb = __reduce_max_sync(0xffffffffu, ub);
            unsigned int candp = (ub == wb) ? p : INVALID_P;     // pad lanes excluded
            unsigned int mp = __reduce_min_sync(0xffffffffu, candp);
            if (lane == 0 && wb != 0u) {
                unsigned long long key =
                    ((unsigned long long)wb << 32) | (unsigned long long)(~mp);
                atomicMax(&s_best[g], key);
            }
        }

        if (p != INVALID_P) {
            const float4 mb = s_box[best_g];
            const int    cv = (best_iou < 0.5f) ? 0 : (s_lab[best_g] + 1);
            float pcx = (pr.x + pr.z) * 0.5f;
            float pcy = (pr.y + pr.w) * 0.5f;
            float pw  = pr.z - pr.x;
            float ph  = pr.w - pr.y;
            float gcx = (mb.x + mb.z) * 0.5f;
            float gcy = (mb.y + mb.w) * 0.5f;
            float gw  = mb.z - mb.x;
            float gh  = mb.w - mb.y;
            float4 loc;
            loc.x = (gcx - pcx) / (0.1f * pw);
            loc.y = (gcy - pcy) / (0.1f * ph);
            loc.z = logf(gw / pw) / 0.2f;
            loc.w = logf(gh / ph) / 0.2f;
            reinterpret_cast<float4*>(out_loc)[(size_t)b * P_NUM + p] = loc;
            if (out_conf) out_conf[(size_t)b * P_NUM + p] = (float)cv;
        }
    }

    __syncthreads();
    if (tid < G_NUM) {
        unsigned long long v = s_best[tid];
        if (v) atomicMax(&g_best[(b << 6) + tid], v);
    }
}

// ---------------- phase E: forced-prior fixup + reset for next call ------
// Replicates scatter semantics: for duplicate priors, the LAST g wins.
__global__ void k_fixup(const float4* __restrict__ priors,
                        const float4* __restrict__ gt_boxes,
                        const int*    __restrict__ gt_labels,
                        float* __restrict__ out_loc,
                        float* __restrict__ out_conf)
{
    __shared__ unsigned int sp[B_NUM * G_NUM];
    const int tid = threadIdx.x;                 // 512 threads = (b,g)
    const unsigned long long key = g_best[tid];
    g_best[tid] = 0ull;                          // restore .bss state
    if (tid < NBINS) {                           // restore bin scratch
        d_bin_count[tid] = 0;
        d_bb_enc[0][tid] = 0; d_bb_enc[1][tid] = 0;
        d_bb_enc[2][tid] = 0; d_bb_enc[3][tid] = 0;
    }
    const unsigned int p = ~((unsigned int)(key & 0xFFFFFFFFull));
    sp[tid] = p;
    __syncthreads();

    if (key == 0ull) return;                     // GT overlapped nothing

    const int b = tid >> 6;
    const int g = tid & 63;
    for (int g2 = g + 1; g2 < G_NUM; g2++)
        if (sp[(b << 6) + g2] == p) return;      // later g claims same prior

    const float4 m  = gt_boxes[b * G_NUM + g];
    const float4 pb = priors[p];
    float pcx = (pb.x + pb.z) * 0.5f;
    float pcy = (pb.y + pb.w) * 0.5f;
    float pw  = pb.z - pb.x;
    float ph  = pb.w - pb.y;
    float gcx = (m.x + m.z) * 0.5f;
    float gcy = (m.y + m.w) * 0.5f;
    float gw  = m.z - m.x;
    float gh  = m.w - m.y;
    float4 loc;
    loc.x = (gcx - pcx) / (0.1f * pw);
    loc.y = (gcy - pcy) / (0.1f * ph);
    loc.z = logf(gw / pw) / 0.2f;
    loc.w = logf(gh / ph) / 0.2f;
    reinterpret_cast<float4*>(out_loc)[(size_t)b * P_NUM + p] = loc;
    if (out_conf) out_conf[(size_t)b * P_NUM + p] = (float)(gt_labels[b * G_NUM + g] + 1);
}

extern "C" void kernel_launch(void* const* d_in, const int* in_sizes, int n_in,
                              void* d_out, int out_size)
{
    const float4* priors    = (const float4*)d_in[0];   // [P,4] f32
    const float4* gt_boxes  = (const float4*)d_in[1];   // [B,G,4] f32
    const int*    gt_labels = (const int*)d_in[2];      // [B,G] i32

    float* out = (float*)d_out;
    float* out_loc  = out;                                           // [B,P,4]
    float* out_conf = (out_size >= B_NUM * P_NUM * 5)
                        ? out + (size_t)B_NUM * P_NUM * 4 : nullptr; // [B,P]

    k_bin      <<<P_NUM / 256, 256>>>(priors);
    k_scan_cand<<<1 + B_NUM, 256>>>(gt_boxes);
    k_scatter  <<<P_NUM / 256, 256>>>();
    dim3 grid(SLOT_CAP / 256, B_NUM);                                // (287, 8)
    k_match    <<<grid, 256>>>(priors, gt_boxes, gt_labels, out_loc, out_conf);
    k_fixup    <<<1, B_NUM * G_NUM>>>(priors, gt_boxes, gt_labels, out_loc, out_conf);
}